// round 12
// baseline (speedup 1.0000x reference)
#include <cuda_runtime.h>
#include <cstdint>

#define BATCH    1024
#define VOCAB    100000
#define DIM      128
#define NSEG     3
#define NBINS    2048
#define HOTCAP   3072
#define BCAP     96
#define NTHREADS 512
#define CUT0 100
#define CUT1 500
#define CUT2 1000
#define TGUESS 2.0f          // rank-1000 of 100k N(0,1) ~ 2.33; P(v>2)~2.3% -> ~2275 cands

#define NV4   (VOCAB / 4)                 // 25000
#define NITER ((NV4 + NTHREADS * 2 - 1) / (NTHREADS * 2))   // 25
#define MSKSZ (NITER * NTHREADS)          // 12800 bytes

__device__ __forceinline__ unsigned mono(float f) {
    unsigned u = __float_as_uint(f);
    return (u & 0x80000000u) ? ~u : (u | 0x80000000u);
}

__device__ __forceinline__ unsigned finebin(unsigned m) {
    unsigned fb = (m - 0xC0000000u) >> 13;       // BASE = mono(2.0f), 2048 bins
    return (fb > (NBINS - 1u)) ? (NBINS - 1u) : fb;
}

// ---------------------------------------------------------------------------
// Scan NBINS-bin histogram descending with shfl; 4 bins per thread.
// ---------------------------------------------------------------------------
__device__ void scan_find(unsigned* hist, unsigned* warpsum, int tid,
                          int* s_bin, int* s_rank)
{
    const int lane = tid & 31, w = tid >> 5;
    unsigned c[4];
    unsigned chunk = 0;
#pragma unroll
    for (int j = 0; j < 4; j++) {
        c[j] = hist[NBINS - 1 - 4 * tid - j];
        chunk += c[j];
    }
    unsigned pfx = chunk;
#pragma unroll
    for (int off = 1; off < 32; off <<= 1) {
        unsigned n = __shfl_up_sync(0xFFFFFFFFu, pfx, off);
        if (lane >= off) pfx += n;
    }
    if (lane == 31) warpsum[w] = pfx;
    __syncthreads();
    if (w == 0) {
        unsigned s = (lane < 16) ? warpsum[lane] : 0u;
#pragma unroll
        for (int off = 1; off < 16; off <<= 1) {
            unsigned n = __shfl_up_sync(0xFFFFFFFFu, s, off);
            if (lane >= off) s += n;
        }
        if (lane < 16) warpsum[lane] = s;
    }
    __syncthreads();
    unsigned wbase = (w > 0) ? warpsum[w - 1] : 0u;
    unsigned incl = wbase + pfx;
    unsigned excl = incl - chunk;
    const unsigned Ks[3] = {CUT0, CUT1, CUT2};
#pragma unroll
    for (int kk = 0; kk < 3; kk++) {
        unsigned K = Ks[kk];
        if (excl < K && K <= incl) {
            unsigned cc = excl;
#pragma unroll
            for (int j = 0; j < 4; j++) {
                unsigned h = c[j];
                if (cc < K && K <= cc + h) {
                    s_bin[kk]  = NBINS - 1 - 4 * tid - j;
                    s_rank[kk] = (int)(K - cc);
                    break;
                }
                cc += h;
            }
        }
    }
    __syncthreads();
}

// ---------------------------------------------------------------------------
// Single fused kernel: one CTA (512 thr) per row.
// pass1: copy + mask-only candidate detection (no per-candidate work in loop)
// phase2: extract candidates from masks -> hot[] + fine hist
// then: in-CTA rh GEMV, exact threshold selection, dot + scatter.
// ---------------------------------------------------------------------------
__global__ void __launch_bounds__(NTHREADS, 4)
rerank_kernel(const float* __restrict__ logits,
              const float* __restrict__ emb,
              const float* __restrict__ hidden,
              const float* __restrict__ W,
              const float* __restrict__ bias,
              float* __restrict__ out)
{
    __shared__ unsigned long long hot[HOTCAP];       // 24 KB
    __shared__ unsigned hist[NBINS];                 // 8 KB
    __shared__ unsigned char s_msk[MSKSZ];           // 12.5 KB candidate masks
    __shared__ unsigned long long bbuf[3][BCAP];     // 2.25 KB boundary-bin members
    __shared__ unsigned warpsum[16];
    __shared__ float rh[NSEG * DIM];
    __shared__ float hrow[DIM];
    __shared__ unsigned long long Tkey[3];
    __shared__ int s_bin[3];
    __shared__ int s_rank[3];
    __shared__ int bcnt[3];
    __shared__ int s_nhot;

    const int row = blockIdx.x;
    const int tid = threadIdx.x;
    const int lane = tid & 31;
    const int wid = tid >> 5;

    for (int i = tid; i < NBINS; i += NTHREADS) hist[i] = 0u;
    for (int i = tid; i < MSKSZ / 4; i += NTHREADS)
        ((unsigned*)s_msk)[i] = 0u;
    if (tid < DIM) hrow[tid] = hidden[(size_t)row * DIM + tid];
    if (tid == 0) { s_nhot = 0; }
    if (tid < 3) bcnt[tid] = 0;
    __syncthreads();

    const float* rowp = logits + (size_t)row * VOCAB;
    const float4* row4 = (const float4*)rowp;
    float4*       out4 = (float4*)(out + (size_t)row * VOCAB);

    // ------- Pass 1: lean streaming copy; mask byte only on prefilter hit ---
    for (int it = 0; it < NITER; it++) {
        int i0 = it * (NTHREADS * 2) + tid;
        int i1 = i0 + NTHREADS;
        bool ok0 = i0 < NV4, ok1 = i1 < NV4;
        float4 v0, v1;
        if (ok0) v0 = __ldcs(&row4[i0]);
        if (ok1) v1 = __ldcs(&row4[i1]);
        if (ok0) __stcs(&out4[i0], v0);
        if (ok1) __stcs(&out4[i1], v1);

        float M0 = ok0 ? fmaxf(fmaxf(v0.x, v0.y), fmaxf(v0.z, v0.w)) : -1e30f;
        float M1 = ok1 ? fmaxf(fmaxf(v1.x, v1.y), fmaxf(v1.z, v1.w)) : -1e30f;
        if (fmaxf(M0, M1) > TGUESS) {                 // ~17% of threads
            unsigned msk = 0;
            if (M0 > TGUESS)
                msk |= (v0.x > TGUESS) | ((v0.y > TGUESS) << 1)
                     | ((v0.z > TGUESS) << 2) | ((v0.w > TGUESS) << 3);
            if (M1 > TGUESS)
                msk |= ((v1.x > TGUESS) << 4) | ((v1.y > TGUESS) << 5)
                     | ((v1.z > TGUESS) << 6) | ((v1.w > TGUESS) << 7);
            s_msk[it * NTHREADS + tid] = (unsigned char)msk;
        }
    }
    __syncthreads();

    // ------- Phase 2: extract candidates from masks (tail, cheap) -----------
    {
        const int b0 = tid * NITER;                   // 25 bytes per thread
        int cnt = 0;
#pragma unroll 5
        for (int j = 0; j < NITER; j++)
            cnt += __popc((unsigned)s_msk[b0 + j]);
        if (cnt) {
            int slot = atomicAdd(&s_nhot, cnt);
            for (int j = 0; j < NITER; j++) {
                unsigned m8 = s_msk[b0 + j];
                if (!m8) continue;
                int b = b0 + j;
                int it = b >> 9, t0 = b & (NTHREADS - 1);
                int e0 = (it * (NTHREADS * 2) + t0) * 4;
                int e1 = e0 + NTHREADS * 4;
                while (m8) {
                    int q = __ffs(m8) - 1;
                    m8 &= m8 - 1;
                    int elem = (q < 4) ? (e0 + q) : (e1 + q - 4);
                    unsigned m = mono(rowp[elem]);
                    if (slot < HOTCAP) {
                        hot[slot] = ((unsigned long long)m << 32) | (unsigned)(~elem);
                        atomicAdd(&hist[finebin(m)], 1u);
                    }
                    slot++;
                }
            }
        }
    }

    // ------- In-CTA rh GEMV: 16 warps x 24 outputs, ILP-4 load groups -------
    {
        const float4* W4 = (const float4*)W;          // [384][32] float4
        const float4* h4 = (const float4*)hrow;
        float4 hv = h4[lane];
        const int o0 = wid * 24;
#pragma unroll
        for (int g = 0; g < 6; g++) {
            float4 wv[4];
#pragma unroll
            for (int k = 0; k < 4; k++)
                wv[k] = W4[(size_t)(o0 + g * 4 + k) * 32 + lane];
#pragma unroll
            for (int k = 0; k < 4; k++) {
                float p = wv[k].x * hv.x + wv[k].y * hv.y
                        + wv[k].z * hv.z + wv[k].w * hv.w;
                p += __shfl_xor_sync(0xFFFFFFFFu, p, 16);
                p += __shfl_xor_sync(0xFFFFFFFFu, p, 8);
                p += __shfl_xor_sync(0xFFFFFFFFu, p, 4);
                p += __shfl_xor_sync(0xFFFFFFFFu, p, 2);
                p += __shfl_xor_sync(0xFFFFFFFFu, p, 1);
                int o = o0 + g * 4 + k;
                if (lane == 0) rh[o] = p + bias[o];
            }
        }
    }
    __syncthreads();

    int nhot = s_nhot;
    bool fast = (nhot >= CUT2) && (nhot <= HOTCAP);

    if (fast) {
        scan_find(hist, warpsum, tid, s_bin, s_rank);
        const int b0 = s_bin[0], b1 = s_bin[1], b2 = s_bin[2];

        // ---- Gather boundary-bin members into tiny buffers (one pass) ----
        for (int i = tid; i < nhot; i += NTHREADS) {
            unsigned long long k = hot[i];
            int bin = (int)finebin((unsigned)(k >> 32));
            if (bin == b0) { int p = atomicAdd(&bcnt[0], 1); if (p < BCAP) bbuf[0][p] = k; }
            if (bin == b1) { int p = atomicAdd(&bcnt[1], 1); if (p < BCAP) bbuf[1][p] = k; }
            if (bin == b2) { int p = atomicAdd(&bcnt[2], 1); if (p < BCAP) bbuf[2][p] = k; }
        }
        __syncthreads();

        // ---- Exact threshold keys: count-greater within each tiny buffer ----
#pragma unroll
        for (int kk = 0; kk < 3; kk++) {
            int n = bcnt[kk];
            if (n <= BCAP) {
                for (int i = tid; i < n; i += NTHREADS) {
                    unsigned long long k = bbuf[kk][i];
                    int cnt = 0;
                    for (int j = 0; j < n; j++)
                        if (bbuf[kk][j] > k) cnt++;
                    if (cnt + 1 == s_rank[kk]) Tkey[kk] = k;
                }
            } else {
                // overflow (astronomically rare): scan the full hot[] set
                const int bk = s_bin[kk];
                for (int i = tid; i < nhot; i += NTHREADS) {
                    unsigned long long k = hot[i];
                    if ((int)finebin((unsigned)(k >> 32)) != bk) continue;
                    int cnt = 0;
                    for (int j = 0; j < nhot; j++) {
                        unsigned long long kj = hot[j];
                        if ((int)finebin((unsigned)(kj >> 32)) == bk && kj > k) cnt++;
                    }
                    if (cnt + 1 == s_rank[kk]) Tkey[kk] = k;
                }
            }
        }
        __syncthreads();
    } else {
        // ------- Fallback: full coarse histogram over the row (rare) -------
        for (int i = tid; i < NBINS; i += NTHREADS) hist[i] = 0u;
        if (tid == 0) s_nhot = 0;
        __syncthreads();
        for (int i = tid; i < NV4; i += NTHREADS) {
            float4 v = row4[i];
            atomicAdd(&hist[mono(v.x) >> 21], 1u);
            atomicAdd(&hist[mono(v.y) >> 21], 1u);
            atomicAdd(&hist[mono(v.z) >> 21], 1u);
            atomicAdd(&hist[mono(v.w) >> 21], 1u);
        }
        __syncthreads();
        scan_find(hist, warpsum, tid, s_bin, s_rank);
        const int cb2 = s_bin[2];
        for (int i = tid; i < NV4; i += NTHREADS) {
            float4 v = row4[i];
            float vals[4] = {v.x, v.y, v.z, v.w};
            int b4 = 4 * i;
#pragma unroll
            for (int j = 0; j < 4; j++) {
                unsigned m = mono(vals[j]);
                if ((int)(m >> 21) >= cb2) {
                    int p = atomicAdd(&s_nhot, 1);
                    if (p < HOTCAP)
                        hot[p] = ((unsigned long long)m << 32) | (unsigned)(~(b4 + j));
                }
            }
        }
        __syncthreads();
        nhot = (s_nhot < HOTCAP) ? s_nhot : HOTCAP;
        const int b0 = s_bin[0], b1 = s_bin[1], b2 = s_bin[2];
        for (int i = tid; i < nhot; i += NTHREADS) {
            unsigned long long k = hot[i];
            int bin = (int)(k >> 53);
            bool m0 = (bin == b0), m1 = (bin == b1), m2 = (bin == b2);
            if (m0 | m1 | m2) {
                int cnt = 0;
                for (int j = 0; j < nhot; j++) {
                    unsigned long long kj = hot[j];
                    if ((int)(kj >> 53) == bin && kj > k) cnt++;
                }
                int r = cnt + 1;
                if (m0 && r == s_rank[0]) Tkey[0] = k;
                if (m1 && r == s_rank[1]) Tkey[1] = k;
                if (m2 && r == s_rank[2]) Tkey[2] = k;
            }
        }
        __syncthreads();
    }

    const unsigned long long T0 = Tkey[0], T1 = Tkey[1], T2 = Tkey[2];

    // ------- Dot phase: 2 candidates per warp per round -------
    const int NW = NTHREADS / 32;
    const float4* emb4 = (const float4*)emb;
    const float4* rh4  = (const float4*)rh;
    float* outrow = out + (size_t)row * VOCAB;

    for (int s = wid * 2; s < nhot; s += NW * 2) {
        unsigned long long k[2];
        bool act[2];
        unsigned idx[2];
        float4 e[2];
        int seg[2];
#pragma unroll
        for (int j = 0; j < 2; j++) {
            int si = s + j;
            k[j] = (si < nhot) ? hot[si] : 0ull;
            act[j] = (k[j] >= T2);
            if (act[j]) {
                seg[j] = (k[j] >= T0) ? 0 : ((k[j] >= T1) ? 1 : 2);
                idx[j] = ~(unsigned)k[j];
                e[j] = emb4[(size_t)idx[j] * (DIM / 4) + lane];
            }
        }
#pragma unroll
        for (int j = 0; j < 2; j++) {
            if (!act[j]) continue;
            float4 r = rh4[seg[j] * (DIM / 4) + lane];
            float p = e[j].x * r.x + e[j].y * r.y + e[j].z * r.z + e[j].w * r.w;
            p += __shfl_xor_sync(0xFFFFFFFFu, p, 16);
            p += __shfl_xor_sync(0xFFFFFFFFu, p, 8);
            p += __shfl_xor_sync(0xFFFFFFFFu, p, 4);
            p += __shfl_xor_sync(0xFFFFFFFFu, p, 2);
            p += __shfl_xor_sync(0xFFFFFFFFu, p, 1);
            if (lane == 0) outrow[idx[j]] = p;
        }
    }
}

extern "C" void kernel_launch(void* const* d_in, const int* in_sizes, int n_in,
                              void* d_out, int out_size)
{
    const float* hidden = nullptr;
    const float* logits = nullptr;
    const float* emb    = nullptr;
    const float* W      = nullptr;
    const float* bias   = nullptr;
    for (int i = 0; i < n_in; i++) {
        switch (in_sizes[i]) {
            case BATCH * DIM:      hidden = (const float*)d_in[i]; break;
            case BATCH * VOCAB:    logits = (const float*)d_in[i]; break;
            case VOCAB * DIM:      emb    = (const float*)d_in[i]; break;
            case NSEG * DIM * DIM: W      = (const float*)d_in[i]; break;
            case NSEG * DIM:       bias   = (const float*)d_in[i]; break;
        }
    }
    float* out = (float*)d_out;

    rerank_kernel<<<BATCH, NTHREADS>>>(logits, emb, hidden, W, bias, out);
}

// round 13
// speedup vs baseline: 1.3831x; 1.3831x over previous
#include <cuda_runtime.h>
#include <cstdint>

#define BATCH    1024
#define VOCAB    100000
#define DIM      128
#define NSEG     3
#define NBINS    2048
#define HOTCAP   3072
#define BCAP     96
#define NTHREADS 512
#define CUT0 100
#define CUT1 500
#define CUT2 1000
#define TGUESS 2.0f          // rank-1000 of 100k N(0,1) ~ 2.33; P(v>2)~2.3% -> ~2275 cands

__device__ __forceinline__ unsigned mono(float f) {
    unsigned u = __float_as_uint(f);
    return (u & 0x80000000u) ? ~u : (u | 0x80000000u);
}

__device__ __forceinline__ unsigned finebin(unsigned m) {
    unsigned fb = (m - 0xC0000000u) >> 13;       // BASE = mono(2.0f), 2048 bins
    return (fb > (NBINS - 1u)) ? (NBINS - 1u) : fb;
}

// ---------------------------------------------------------------------------
// Scan NBINS-bin histogram descending with shfl; 4 bins per thread.
// ---------------------------------------------------------------------------
__device__ void scan_find(unsigned* hist, unsigned* warpsum, int tid,
                          int* s_bin, int* s_rank)
{
    const int lane = tid & 31, w = tid >> 5;
    unsigned c[4];
    unsigned chunk = 0;
#pragma unroll
    for (int j = 0; j < 4; j++) {
        c[j] = hist[NBINS - 1 - 4 * tid - j];
        chunk += c[j];
    }
    unsigned pfx = chunk;
#pragma unroll
    for (int off = 1; off < 32; off <<= 1) {
        unsigned n = __shfl_up_sync(0xFFFFFFFFu, pfx, off);
        if (lane >= off) pfx += n;
    }
    if (lane == 31) warpsum[w] = pfx;
    __syncthreads();
    if (w == 0) {
        unsigned s = (lane < 16) ? warpsum[lane] : 0u;
#pragma unroll
        for (int off = 1; off < 16; off <<= 1) {
            unsigned n = __shfl_up_sync(0xFFFFFFFFu, s, off);
            if (lane >= off) s += n;
        }
        if (lane < 16) warpsum[lane] = s;
    }
    __syncthreads();
    unsigned wbase = (w > 0) ? warpsum[w - 1] : 0u;
    unsigned incl = wbase + pfx;
    unsigned excl = incl - chunk;
    const unsigned Ks[3] = {CUT0, CUT1, CUT2};
#pragma unroll
    for (int kk = 0; kk < 3; kk++) {
        unsigned K = Ks[kk];
        if (excl < K && K <= incl) {
            unsigned cc = excl;
#pragma unroll
            for (int j = 0; j < 4; j++) {
                unsigned h = c[j];
                if (cc < K && K <= cc + h) {
                    s_bin[kk]  = NBINS - 1 - 4 * tid - j;
                    s_rank[kk] = (int)(K - cc);
                    break;
                }
                cc += h;
            }
        }
    }
    __syncthreads();
}

__device__ __forceinline__ void push_cand(float v, int gi,
                                          unsigned long long* hot, unsigned* hist,
                                          int& slot)
{
    unsigned m = mono(v);
    if (slot < HOTCAP) {
        hot[slot] = ((unsigned long long)m << 32) | (unsigned)(~gi);
        atomicAdd(&hist[finebin(m)], 1u);
    }
    slot++;
}

__device__ __forceinline__ void push_group(float4 v, unsigned m4, int gi,
                                           unsigned long long* hot, unsigned* hist,
                                           int& slot)
{
    if (m4 & 1) push_cand(v.x, gi + 0, hot, hist, slot);
    if (m4 & 2) push_cand(v.y, gi + 1, hot, hist, slot);
    if (m4 & 4) push_cand(v.z, gi + 2, hot, hist, slot);
    if (m4 & 8) push_cand(v.w, gi + 3, hot, hist, slot);
}

// ---------------------------------------------------------------------------
// Single fused kernel: one CTA (512 thr) per row.
// copy + collect (pass 1) -> in-CTA rh GEMV (ILP-4) -> select -> dot+scatter.
// ---------------------------------------------------------------------------
__global__ void __launch_bounds__(NTHREADS, 4)
rerank_kernel(const float* __restrict__ logits,
              const float* __restrict__ emb,
              const float* __restrict__ hidden,
              const float* __restrict__ W,
              const float* __restrict__ bias,
              float* __restrict__ out)
{
    __shared__ unsigned long long hot[HOTCAP];       // 24 KB
    __shared__ unsigned hist[NBINS];                 // 8 KB
    __shared__ unsigned long long bbuf[3][BCAP];     // 2.25 KB boundary-bin members
    __shared__ unsigned warpsum[16];
    __shared__ float rh[NSEG * DIM];
    __shared__ float sbias[NSEG * DIM];
    __shared__ float hrow[DIM];
    __shared__ unsigned long long Tkey[3];
    __shared__ int s_bin[3];
    __shared__ int s_rank[3];
    __shared__ int bcnt[3];
    __shared__ int s_nhot;

    const int row = blockIdx.x;
    const int tid = threadIdx.x;
    const int lane = tid & 31;
    const int wid = tid >> 5;

    for (int i = tid; i < NBINS; i += NTHREADS) hist[i] = 0u;
    if (tid < DIM) hrow[tid] = hidden[(size_t)row * DIM + tid];
    if (tid < NSEG * DIM) sbias[tid] = bias[tid];
    if (tid == 0) { s_nhot = 0; }
    if (tid < 3) bcnt[tid] = 0;
    __syncthreads();

    const float4* row4 = (const float4*)(logits + (size_t)row * VOCAB);
    float4*       out4 = (float4*)(out + (size_t)row * VOCAB);
    const int NV4 = VOCAB / 4;   // 25000

    // ------- Pass 1: 2-way batched stream copy + warp-aggregated collect -----
    for (int base = 0; base < NV4; base += NTHREADS * 2) {
        int i0 = base + tid;
        int i1 = base + NTHREADS + tid;
        bool ok0 = i0 < NV4, ok1 = i1 < NV4;
        float4 v0, v1;
        if (ok0) v0 = __ldcs(&row4[i0]);
        if (ok1) v1 = __ldcs(&row4[i1]);
        if (ok0) __stcs(&out4[i0], v0);
        if (ok1) __stcs(&out4[i1], v1);

        // fmax prefilter
        float M0 = ok0 ? fmaxf(fmaxf(v0.x, v0.y), fmaxf(v0.z, v0.w)) : -1e30f;
        float M1 = ok1 ? fmaxf(fmaxf(v1.x, v1.y), fmaxf(v1.z, v1.w)) : -1e30f;
        unsigned msk = 0;
        int cnt = 0;
        if (fmaxf(M0, M1) > TGUESS) {
            if (M0 > TGUESS)
                msk |= (v0.x > TGUESS) | ((v0.y > TGUESS) << 1)
                     | ((v0.z > TGUESS) << 2) | ((v0.w > TGUESS) << 3);
            if (M1 > TGUESS)
                msk |= ((v1.x > TGUESS) << 4) | ((v1.y > TGUESS) << 5)
                     | ((v1.z > TGUESS) << 6) | ((v1.w > TGUESS) << 7);
            cnt = __popc(msk);
        }

        if (__ballot_sync(0xFFFFFFFFu, cnt > 0)) {
            int pfx = cnt;
#pragma unroll
            for (int off = 1; off < 32; off <<= 1) {
                int n = __shfl_up_sync(0xFFFFFFFFu, pfx, off);
                if (lane >= off) pfx += n;
            }
            int total = __shfl_sync(0xFFFFFFFFu, pfx, 31);
            int wbase = 0;
            if (lane == 31) wbase = atomicAdd(&s_nhot, total);
            wbase = __shfl_sync(0xFFFFFFFFu, wbase, 31);
            int slot = wbase + pfx - cnt;
            if (cnt) {
                push_group(v0, msk & 0xF,        4 * i0, hot, hist, slot);
                push_group(v1, (msk >> 4) & 0xF, 4 * i1, hot, hist, slot);
            }
        }
    }
    __syncthreads();

    // ------- In-CTA rh GEMV: 16 warps x 24 outputs, ILP-4 load groups -------
    {
        const float4* W4 = (const float4*)W;          // [384][32] float4
        const float4* h4 = (const float4*)hrow;
        float4 hv = h4[lane];
        const int o0 = wid * 24;
#pragma unroll
        for (int g = 0; g < 6; g++) {
            float4 wv[4];
#pragma unroll
            for (int k = 0; k < 4; k++)
                wv[k] = W4[(size_t)(o0 + g * 4 + k) * 32 + lane];
#pragma unroll
            for (int k = 0; k < 4; k++) {
                float p = wv[k].x * hv.x + wv[k].y * hv.y
                        + wv[k].z * hv.z + wv[k].w * hv.w;
                p += __shfl_xor_sync(0xFFFFFFFFu, p, 16);
                p += __shfl_xor_sync(0xFFFFFFFFu, p, 8);
                p += __shfl_xor_sync(0xFFFFFFFFu, p, 4);
                p += __shfl_xor_sync(0xFFFFFFFFu, p, 2);
                p += __shfl_xor_sync(0xFFFFFFFFu, p, 1);
                int o = o0 + g * 4 + k;
                if (lane == 0) rh[o] = p + sbias[o];
            }
        }
    }
    // (rh[] consumed after the selection barriers below)

    int nhot = s_nhot;
    bool fast = (nhot >= CUT2) && (nhot <= HOTCAP);

    if (fast) {
        scan_find(hist, warpsum, tid, s_bin, s_rank);
        const int b0 = s_bin[0], b1 = s_bin[1], b2 = s_bin[2];

        // ---- Gather boundary-bin members into tiny buffers (one pass) ----
        for (int i = tid; i < nhot; i += NTHREADS) {
            unsigned long long k = hot[i];
            int bin = (int)finebin((unsigned)(k >> 32));
            if (bin == b0) { int p = atomicAdd(&bcnt[0], 1); if (p < BCAP) bbuf[0][p] = k; }
            if (bin == b1) { int p = atomicAdd(&bcnt[1], 1); if (p < BCAP) bbuf[1][p] = k; }
            if (bin == b2) { int p = atomicAdd(&bcnt[2], 1); if (p < BCAP) bbuf[2][p] = k; }
        }
        __syncthreads();

        // ---- Exact threshold keys: count-greater within each tiny buffer ----
#pragma unroll
        for (int kk = 0; kk < 3; kk++) {
            int n = bcnt[kk];
            if (n <= BCAP) {
                for (int i = tid; i < n; i += NTHREADS) {
                    unsigned long long k = bbuf[kk][i];
                    int cnt = 0;
                    for (int j = 0; j < n; j++)
                        if (bbuf[kk][j] > k) cnt++;
                    if (cnt + 1 == s_rank[kk]) Tkey[kk] = k;
                }
            } else {
                // overflow (astronomically rare): scan the full hot[] set
                const int bk = s_bin[kk];
                for (int i = tid; i < nhot; i += NTHREADS) {
                    unsigned long long k = hot[i];
                    if ((int)finebin((unsigned)(k >> 32)) != bk) continue;
                    int cnt = 0;
                    for (int j = 0; j < nhot; j++) {
                        unsigned long long kj = hot[j];
                        if ((int)finebin((unsigned)(kj >> 32)) == bk && kj > k) cnt++;
                    }
                    if (cnt + 1 == s_rank[kk]) Tkey[kk] = k;
                }
            }
        }
        __syncthreads();
    } else {
        // ------- Fallback: full coarse histogram over the row (rare) -------
        for (int i = tid; i < NBINS; i += NTHREADS) hist[i] = 0u;
        if (tid == 0) s_nhot = 0;
        __syncthreads();
        for (int i = tid; i < NV4; i += NTHREADS) {
            float4 v = row4[i];
            atomicAdd(&hist[mono(v.x) >> 21], 1u);
            atomicAdd(&hist[mono(v.y) >> 21], 1u);
            atomicAdd(&hist[mono(v.z) >> 21], 1u);
            atomicAdd(&hist[mono(v.w) >> 21], 1u);
        }
        __syncthreads();
        scan_find(hist, warpsum, tid, s_bin, s_rank);
        const int cb2 = s_bin[2];
        for (int i = tid; i < NV4; i += NTHREADS) {
            float4 v = row4[i];
            float vals[4] = {v.x, v.y, v.z, v.w};
            int b4 = 4 * i;
#pragma unroll
            for (int j = 0; j < 4; j++) {
                unsigned m = mono(vals[j]);
                if ((int)(m >> 21) >= cb2) {
                    int p = atomicAdd(&s_nhot, 1);
                    if (p < HOTCAP)
                        hot[p] = ((unsigned long long)m << 32) | (unsigned)(~(b4 + j));
                }
            }
        }
        __syncthreads();
        nhot = (s_nhot < HOTCAP) ? s_nhot : HOTCAP;
        const int b0 = s_bin[0], b1 = s_bin[1], b2 = s_bin[2];
        for (int i = tid; i < nhot; i += NTHREADS) {
            unsigned long long k = hot[i];
            int bin = (int)(k >> 53);
            bool m0 = (bin == b0), m1 = (bin == b1), m2 = (bin == b2);
            if (m0 | m1 | m2) {
                int cnt = 0;
                for (int j = 0; j < nhot; j++) {
                    unsigned long long kj = hot[j];
                    if ((int)(kj >> 53) == bin && kj > k) cnt++;
                }
                int r = cnt + 1;
                if (m0 && r == s_rank[0]) Tkey[0] = k;
                if (m1 && r == s_rank[1]) Tkey[1] = k;
                if (m2 && r == s_rank[2]) Tkey[2] = k;
            }
        }
        __syncthreads();
    }

    const unsigned long long T0 = Tkey[0], T1 = Tkey[1], T2 = Tkey[2];

    // ------- Dot phase: 2 candidates per warp per round -------
    const int NW = NTHREADS / 32;
    const float4* emb4 = (const float4*)emb;
    const float4* rh4  = (const float4*)rh;
    float* outrow = out + (size_t)row * VOCAB;

    for (int s = wid * 2; s < nhot; s += NW * 2) {
        unsigned long long k[2];
        bool act[2];
        unsigned idx[2];
        float4 e[2];
        int seg[2];
#pragma unroll
        for (int j = 0; j < 2; j++) {
            int si = s + j;
            k[j] = (si < nhot) ? hot[si] : 0ull;
            act[j] = (k[j] >= T2);
            if (act[j]) {
                seg[j] = (k[j] >= T0) ? 0 : ((k[j] >= T1) ? 1 : 2);
                idx[j] = ~(unsigned)k[j];
                e[j] = emb4[(size_t)idx[j] * (DIM / 4) + lane];
            }
        }
#pragma unroll
        for (int j = 0; j < 2; j++) {
            if (!act[j]) continue;
            float4 r = rh4[seg[j] * (DIM / 4) + lane];
            float p = e[j].x * r.x + e[j].y * r.y + e[j].z * r.z + e[j].w * r.w;
            p += __shfl_xor_sync(0xFFFFFFFFu, p, 16);
            p += __shfl_xor_sync(0xFFFFFFFFu, p, 8);
            p += __shfl_xor_sync(0xFFFFFFFFu, p, 4);
            p += __shfl_xor_sync(0xFFFFFFFFu, p, 2);
            p += __shfl_xor_sync(0xFFFFFFFFu, p, 1);
            if (lane == 0) outrow[idx[j]] = p;
        }
    }
}

extern "C" void kernel_launch(void* const* d_in, const int* in_sizes, int n_in,
                              void* d_out, int out_size)
{
    const float* hidden = nullptr;
    const float* logits = nullptr;
    const float* emb    = nullptr;
    const float* W      = nullptr;
    const float* bias   = nullptr;
    for (int i = 0; i < n_in; i++) {
        switch (in_sizes[i]) {
            case BATCH * DIM:      hidden = (const float*)d_in[i]; break;
            case BATCH * VOCAB:    logits = (const float*)d_in[i]; break;
            case VOCAB * DIM:      emb    = (const float*)d_in[i]; break;
            case NSEG * DIM * DIM: W      = (const float*)d_in[i]; break;
            case NSEG * DIM:       bias   = (const float*)d_in[i]; break;
        }
    }
    float* out = (float*)d_out;

    rerank_kernel<<<BATCH, NTHREADS>>>(logits, emb, hidden, W, bias, out);
}